// round 10
// baseline (speedup 1.0000x reference)
#include <cuda_runtime.h>
#include <cuda_fp16.h>
#include <cstdint>

// VQCodebook: single-product fp16 HMMA approx distances + exact fp32 rescue.
// Out (f32): [z_q_st 65536*64][indices 65536][loss 1]

#define N_TOK   65536
#define DIM     64
#define NCODE   1024
#define OUT_IDX (N_TOK * DIM)
#define OUT_LOSS (OUT_IDX + N_TOK)
#define THRESH  2e-4f

__device__ float  g_s2[NCODE];
__device__ uint2  g_bfrag[8 * 16 * 4 * 32];   // [chunk][nt][ks][lane] = {b0,b1} fp16x2
__device__ int    g_idx[N_TOK];
__device__ int    g_list[N_TOK];
__device__ int    g_cnt;
__device__ double g_lacc;

__device__ __forceinline__ uint32_t smem_u32(const void* p) {
    uint32_t a;
    asm("{ .reg .u64 t; cvta.to.shared.u64 t, %1; cvt.u32.u64 %0, t; }" : "=r"(a) : "l"(p));
    return a;
}
__device__ __forceinline__ uint32_t h2(float x, float y) {
    __half2 h = __floats2half2_rn(x, y);
    return *reinterpret_cast<uint32_t*>(&h);
}
__device__ __forceinline__ void mma_f16(float& c0, float& c1, float& c2, float& c3,
                                        uint32_t a0, uint32_t a1, uint32_t a2, uint32_t a3,
                                        uint32_t b0, uint32_t b1) {
    asm volatile("mma.sync.aligned.m16n8k16.row.col.f32.f16.f16.f32 "
                 "{%0,%1,%2,%3}, {%4,%5,%6,%7}, {%8,%9}, {%0,%1,%2,%3};"
                 : "+f"(c0), "+f"(c1), "+f"(c2), "+f"(c3)
                 : "r"(a0), "r"(a1), "r"(a2), "r"(a3), "r"(b0), "r"(b1));
}
#define CP_ASYNC16(dst, src) \
    asm volatile("cp.async.cg.shared.global [%0], [%1], 16;" :: "r"(dst), "l"(src))
#define CP_COMMIT() asm volatile("cp.async.commit_group;" ::: "memory")
#define CP_WAIT0()  asm volatile("cp.async.wait_group 0;" ::: "memory")

// -------- k_prep: exact code norms + fp16 fragment-layout codebook ---------
__global__ void k_prep(const float* __restrict__ cb) {
    int k = blockIdx.x * blockDim.x + threadIdx.x;
    if (k == 0) { g_lacc = 0.0; g_cnt = 0; }
    if (k >= NCODE) return;
    const float* r = cb + (size_t)k * DIM;
    float s = 0.0f;
#pragma unroll
    for (int d = 0; d < DIM; ++d)
        s = __fadd_rn(s, __fmul_rn(r[d], r[d]));
    g_s2[k] = s;

    const int chunk = k >> 7, cc = k & 127, nt = cc >> 3, n = cc & 7;
#pragma unroll
    for (int ks = 0; ks < 4; ++ks) {
        const int base = 16 * ks;
#pragma unroll
        for (int tg = 0; tg < 4; ++tg) {
            uint32_t b0 = h2(r[base + 2 * tg],     r[base + 2 * tg + 1]);
            uint32_t b1 = h2(r[base + 8 + 2 * tg], r[base + 8 + 2 * tg + 1]);
            g_bfrag[(((chunk * 16 + nt) * 4 + ks) * 32) + n * 4 + tg] = make_uint2(b0, b1);
        }
    }
}

// -------- k_mma: 128 tokens/CTA, single-product fp16 HMMA ------------------
__global__ void __launch_bounds__(256, 4) k_mma(const float* __restrict__ z) {
    __shared__ __align__(16) uint2 bf[2][2048];   // 2 x 16KB
    __shared__ float s2s[NCODE];                  // 4KB
    const uint32_t sbf = smem_u32(bf);
    const int tid = threadIdx.x;
    const int w = tid >> 5, lane = tid & 31;
    const int g = lane >> 2, tg = lane & 3;
    const int tok0 = blockIdx.x * 128;

    // stage chunk 0 into buf0 (16KB = 1024 uint4)
    {
        const uint4* src = reinterpret_cast<const uint4*>(g_bfrag);
#pragma unroll
        for (int i = 0; i < 4; ++i)
            CP_ASYNC16(sbf + (uint32_t)(tid + i * 256) * 16, src + tid + i * 256);
        CP_COMMIT();
    }
    for (int i = tid; i < NCODE; i += 256) s2s[i] = g_s2[i];

    // A fragments (fp16) for this warp's 16 tokens
    const int r0 = tok0 + w * 16 + g, r1 = r0 + 8;
    uint32_t a[4][4];
#pragma unroll
    for (int ks = 0; ks < 4; ++ks) {
        const float* p0 = z + (size_t)r0 * DIM + ks * 16;
        const float* p1 = z + (size_t)r1 * DIM + ks * 16;
        float2 x0 = *(const float2*)(p0 + 2 * tg);
        float2 x1 = *(const float2*)(p1 + 2 * tg);
        float2 x2 = *(const float2*)(p0 + 8 + 2 * tg);
        float2 x3 = *(const float2*)(p1 + 8 + 2 * tg);
        a[ks][0] = h2(x0.x, x0.y);
        a[ks][1] = h2(x1.x, x1.y);
        a[ks][2] = h2(x2.x, x2.y);
        a[ks][3] = h2(x3.x, x3.y);
    }
    CP_WAIT0();
    __syncthreads();

    float best0 = 3.402823466e38f, sec0 = 3.402823466e38f;
    float best1 = 3.402823466e38f, sec1 = 3.402823466e38f;
    int bi0 = 0, bi1 = 0;

#pragma unroll 1
    for (int c = 0; c < 8; ++c) {
        if (c < 7) {
            const uint4* src = reinterpret_cast<const uint4*>(g_bfrag) + (c + 1) * 1024;
            uint32_t dst = sbf + (uint32_t)((c + 1) & 1) * 16384u;
#pragma unroll
            for (int i = 0; i < 4; ++i)
                CP_ASYNC16(dst + (uint32_t)(tid + i * 256) * 16, src + tid + i * 256);
            CP_COMMIT();
        }
        const uint2* bp = bf[c & 1] + lane;
        const float* s2c = s2s + c * 128;
#pragma unroll 1
        for (int nt = 0; nt < 16; nt += 4) {
            float acc[4][4];
#pragma unroll
            for (int j = 0; j < 4; ++j)
                acc[j][0] = acc[j][1] = acc[j][2] = acc[j][3] = 0.0f;
#pragma unroll
            for (int ks = 0; ks < 4; ++ks) {
#pragma unroll
                for (int j = 0; j < 4; ++j) {
                    uint2 B = bp[((nt + j) * 4 + ks) * 32];
                    mma_f16(acc[j][0], acc[j][1], acc[j][2], acc[j][3],
                            a[ks][0], a[ks][1], a[ks][2], a[ks][3], B.x, B.y);
                }
            }
#pragma unroll
            for (int j = 0; j < 4; ++j) {
                const int ntx = nt + j;
                const int j0 = c * 128 + ntx * 8 + 2 * tg;
                const float s2x = s2c[ntx * 8 + 2 * tg];
                const float s2y = s2c[ntx * 8 + 2 * tg + 1];
                // d~ = s2 - 2e  (s1 constant per token: irrelevant for argmin/gap)
                float d00 = __fmaf_rn(-2.0f, acc[j][0], s2x);
                float d01 = __fmaf_rn(-2.0f, acc[j][1], s2y);
                float d10 = __fmaf_rn(-2.0f, acc[j][2], s2x);
                float d11 = __fmaf_rn(-2.0f, acc[j][3], s2y);
                if (d00 < best0) { sec0 = best0; best0 = d00; bi0 = j0; }
                else if (d00 < sec0) sec0 = d00;
                if (d01 < best0) { sec0 = best0; best0 = d01; bi0 = j0 + 1; }
                else if (d01 < sec0) sec0 = d01;
                if (d10 < best1) { sec1 = best1; best1 = d10; bi1 = j0; }
                else if (d10 < sec1) sec1 = d10;
                if (d11 < best1) { sec1 = best1; best1 = d11; bi1 = j0 + 1; }
                else if (d11 < sec1) sec1 = d11;
            }
        }
        CP_WAIT0();
        __syncthreads();
    }

    // merge (best, second, idx) across the 4 tg-lanes of each row-group
#pragma unroll
    for (int m = 1; m <= 2; m <<= 1) {
        float ob = __shfl_xor_sync(0xffffffffu, best0, m);
        float os = __shfl_xor_sync(0xffffffffu, sec0, m);
        int   oi = __shfl_xor_sync(0xffffffffu, bi0, m);
        if (ob < best0 || (ob == best0 && oi < bi0)) { sec0 = fminf(best0, os); best0 = ob; bi0 = oi; }
        else sec0 = fminf(sec0, ob);
        ob = __shfl_xor_sync(0xffffffffu, best1, m);
        os = __shfl_xor_sync(0xffffffffu, sec1, m);
        oi = __shfl_xor_sync(0xffffffffu, bi1, m);
        if (ob < best1 || (ob == best1 && oi < bi1)) { sec1 = fminf(best1, os); best1 = ob; bi1 = oi; }
        else sec1 = fminf(sec1, ob);
    }
    if (tg == 0) {
        g_idx[r0] = bi0;
        g_idx[r1] = bi1;
        if (__fsub_rn(sec0, best0) <= THRESH) { int p = atomicAdd(&g_cnt, 1); g_list[p] = r0; }
        if (__fsub_rn(sec1, best1) <= THRESH) { int p = atomicAdd(&g_cnt, 1); g_list[p] = r1; }
    }
}

// -------- k_rescue: exact rescore of flagged tokens (R5 rounding chain) ----
__global__ void __launch_bounds__(128) k_rescue(const float* __restrict__ z,
                                                const float* __restrict__ cb) {
    __shared__ float cbs[64 * 64];
    __shared__ float s2s[64];
    __shared__ float zs[16][64];
    __shared__ float s1s[16];
    __shared__ int   toks[16];
    const int tid = threadIdx.x;
    const int cnt = g_cnt;

    for (int base = blockIdx.x * 16; base < cnt; base += gridDim.x * 16) {
        int nb = cnt - base; if (nb > 16) nb = 16;
        __syncthreads();
        if (tid < 16) toks[tid] = g_list[base + (tid < nb ? tid : 0)];
        __syncthreads();
        for (int i = tid; i < nb * 64; i += 128) {
            int t = i >> 6, d = i & 63;
            zs[t][d] = z[(size_t)toks[t] * 64 + d];
        }
        __syncthreads();
        if (tid < nb) {
            float s = 0.0f;
#pragma unroll
            for (int d = 0; d < 64; d++)
                s = __fadd_rn(s, __fmul_rn(zs[tid][d], zs[tid][d]));
            s1s[tid] = s;
        }
        float best = 3.402823466e38f;
        int bi = NCODE;
        const int tb = tid >> 3, sl = tid & 7;
        for (int c0 = 0; c0 < NCODE; c0 += 64) {
            __syncthreads();
            for (int i = tid; i < 64 * 64; i += 128) cbs[i] = cb[c0 * 64 + i];
            if (tid < 64) s2s[tid] = g_s2[c0 + tid];
            __syncthreads();
            if (tb < nb) {
#pragma unroll
                for (int half = 0; half < 2; ++half) {
                    const int k0 = sl + half * 32;
                    const float* cr0 = &cbs[k0 * 64];
                    const float* cr1 = &cbs[(k0 + 8) * 64];
                    const float* cr2 = &cbs[(k0 + 16) * 64];
                    const float* cr3 = &cbs[(k0 + 24) * 64];
                    float e0 = 0.f, e1 = 0.f, e2 = 0.f, e3 = 0.f;  // 4 exact chains
#pragma unroll
                    for (int d = 0; d < 64; d++) {
                        float zv = zs[tb][d];
                        e0 = __fmaf_rn(zv, cr0[d], e0);
                        e1 = __fmaf_rn(zv, cr1[d], e1);
                        e2 = __fmaf_rn(zv, cr2[d], e2);
                        e3 = __fmaf_rn(zv, cr3[d], e3);
                    }
                    float d0 = __fsub_rn(__fadd_rn(s1s[tb], s2s[k0]),      __fmul_rn(2.0f, e0));
                    float d1 = __fsub_rn(__fadd_rn(s1s[tb], s2s[k0 + 8]),  __fmul_rn(2.0f, e1));
                    float d2 = __fsub_rn(__fadd_rn(s1s[tb], s2s[k0 + 16]), __fmul_rn(2.0f, e2));
                    float d3 = __fsub_rn(__fadd_rn(s1s[tb], s2s[k0 + 24]), __fmul_rn(2.0f, e3));
                    if (d0 < best) { best = d0; bi = c0 + k0; }
                    if (d1 < best) { best = d1; bi = c0 + k0 + 8; }
                    if (d2 < best) { best = d2; bi = c0 + k0 + 16; }
                    if (d3 < best) { best = d3; bi = c0 + k0 + 24; }
                }
            }
        }
#pragma unroll
        for (int m = 4; m; m >>= 1) {
            float ob = __shfl_xor_sync(0xffffffffu, best, m);
            int   oi = __shfl_xor_sync(0xffffffffu, bi, m);
            if (ob < best || (ob == best && oi < bi)) { best = ob; bi = oi; }
        }
        if (sl == 0 && tb < nb) g_idx[toks[tb]] = bi;
    }
}

// -------- k_gather: 2 threads/token, warp-shuffle loss reduce ---------------
__global__ void __launch_bounds__(256) k_gather(const float* __restrict__ z,
                                                const float* __restrict__ cb,
                                                float* __restrict__ out) {
    const int u = blockIdx.x * 256 + threadIdx.x;   // [0, N_TOK*2)
    const int tok = u >> 1, half = u & 1;
    const int idx = g_idx[tok];
    const float4* zp = (const float4*)(z + (size_t)tok * 64 + half * 32);
    const float4* cp = (const float4*)(cb + (size_t)idx * 64 + half * 32);
    float4* op = (float4*)(out + (size_t)tok * 64 + half * 32);
    double ls = 0.0;
#pragma unroll
    for (int q = 0; q < 8; ++q) {
        float4 cv = cp[q], zv = zp[q], w;
        float df;
        df = __fsub_rn(cv.x, zv.x); w.x = __fadd_rn(zv.x, df); ls += (double)__fmul_rn(df, df);
        df = __fsub_rn(cv.y, zv.y); w.y = __fadd_rn(zv.y, df); ls += (double)__fmul_rn(df, df);
        df = __fsub_rn(cv.z, zv.z); w.z = __fadd_rn(zv.z, df); ls += (double)__fmul_rn(df, df);
        df = __fsub_rn(cv.w, zv.w); w.w = __fadd_rn(zv.w, df); ls += (double)__fmul_rn(df, df);
        op[q] = w;
    }
    if (half == 0) out[OUT_IDX + tok] = (float)idx;
#pragma unroll
    for (int m = 16; m; m >>= 1)
        ls += __shfl_xor_sync(0xffffffffu, ls, m);
    if ((threadIdx.x & 31) == 0) atomicAdd(&g_lacc, ls);
}

__global__ void k_fin(float* __restrict__ out) {
    double m = g_lacc / (double)((double)N_TOK * (double)DIM);
    float mf = (float)m;
    out[OUT_LOSS] = __fadd_rn(mf, mf);
}

extern "C" void kernel_launch(void* const* d_in, const int* in_sizes, int n_in,
                              void* d_out, int out_size) {
    const float* z = (const float*)d_in[0];
    const float* cb = (const float*)d_in[1];
    float* out = (float*)d_out;

    k_prep<<<8, 128>>>(cb);
    k_mma<<<N_TOK / 128, 256>>>(z);
    k_rescue<<<148, 128>>>(z, cb);
    k_gather<<<N_TOK * 2 / 256, 256>>>(z, cb, out);
    k_fin<<<1, 1>>>(out);
}

// round 11
// speedup vs baseline: 1.0010x; 1.0010x over previous
#include <cuda_runtime.h>
#include <cuda_fp16.h>
#include <cstdint>

// VQCodebook: single-product fp16 HMMA approx distances + exact fp32 rescue.
// Out (f32): [z_q_st 65536*64][indices 65536][loss 1]

#define N_TOK   65536
#define DIM     64
#define NCODE   1024
#define OUT_IDX (N_TOK * DIM)
#define OUT_LOSS (OUT_IDX + N_TOK)
#define THRESH  2e-4f

__device__ float  g_s2[NCODE];
__device__ uint2  g_bfrag[8 * 16 * 4 * 32];   // [chunk][nt][ks][lane] = {b0,b1} fp16x2
__device__ int    g_idx[N_TOK];
__device__ int    g_list[N_TOK];
__device__ int    g_cnt;
__device__ double g_lacc;

__device__ __forceinline__ uint32_t smem_u32(const void* p) {
    uint32_t a;
    asm("{ .reg .u64 t; cvta.to.shared.u64 t, %1; cvt.u32.u64 %0, t; }" : "=r"(a) : "l"(p));
    return a;
}
__device__ __forceinline__ uint32_t h2(float x, float y) {
    __half2 h = __floats2half2_rn(x, y);
    return *reinterpret_cast<uint32_t*>(&h);
}
__device__ __forceinline__ void mma_f16(float& c0, float& c1, float& c2, float& c3,
                                        uint32_t a0, uint32_t a1, uint32_t a2, uint32_t a3,
                                        uint32_t b0, uint32_t b1) {
    asm volatile("mma.sync.aligned.m16n8k16.row.col.f32.f16.f16.f32 "
                 "{%0,%1,%2,%3}, {%4,%5,%6,%7}, {%8,%9}, {%0,%1,%2,%3};"
                 : "+f"(c0), "+f"(c1), "+f"(c2), "+f"(c3)
                 : "r"(a0), "r"(a1), "r"(a2), "r"(a3), "r"(b0), "r"(b1));
}
#define CP_ASYNC16(dst, src) \
    asm volatile("cp.async.cg.shared.global [%0], [%1], 16;" :: "r"(dst), "l"(src))
#define CP_COMMIT() asm volatile("cp.async.commit_group;" ::: "memory")
#define CP_WAIT0()  asm volatile("cp.async.wait_group 0;" ::: "memory")

// -------- k_prep: exact code norms + fp16 fragment-layout codebook ---------
// 16 threads per code: sub 0..15 -> (ks = sub>>2, tg = sub&3) packs one uint2;
// sub 0 additionally computes the exact sequential-fold norm.
__global__ void __launch_bounds__(256) k_prep(const float* __restrict__ cb) {
    const int t = blockIdx.x * blockDim.x + threadIdx.x;   // [0, NCODE*16)
    if (t == 0) { g_lacc = 0.0; g_cnt = 0; }
    const int k = t >> 4, sub = t & 15;
    if (k >= NCODE) return;
    const float* r = cb + (size_t)k * DIM;

    if (sub == 0) {
        float s = 0.0f;
#pragma unroll
        for (int d = 0; d < DIM; ++d)
            s = __fadd_rn(s, __fmul_rn(r[d], r[d]));
        g_s2[k] = s;
    }
    const int ks = sub >> 2, tg = sub & 3;
    const int base = 16 * ks;
    uint32_t b0 = h2(r[base + 2 * tg],     r[base + 2 * tg + 1]);
    uint32_t b1 = h2(r[base + 8 + 2 * tg], r[base + 8 + 2 * tg + 1]);
    const int chunk = k >> 7, cc = k & 127, nt = cc >> 3, n = cc & 7;
    g_bfrag[(((chunk * 16 + nt) * 4 + ks) * 32) + n * 4 + tg] = make_uint2(b0, b1);
}

// -------- k_mma: 128 tokens/CTA, single-product fp16 HMMA ------------------
__global__ void __launch_bounds__(256, 2) k_mma(const float* __restrict__ z) {
    __shared__ __align__(16) uint2 bf[2][2048];   // 2 x 16KB
    __shared__ float s2s[NCODE];                  // 4KB
    const uint32_t sbf = smem_u32(bf);
    const int tid = threadIdx.x;
    const int w = tid >> 5, lane = tid & 31;
    const int g = lane >> 2, tg = lane & 3;
    const int tok0 = blockIdx.x * 128;

    // stage chunk 0 into buf0 (16KB = 1024 uint4)
    {
        const uint4* src = reinterpret_cast<const uint4*>(g_bfrag);
#pragma unroll
        for (int i = 0; i < 4; ++i)
            CP_ASYNC16(sbf + (uint32_t)(tid + i * 256) * 16, src + tid + i * 256);
        CP_COMMIT();
    }
    for (int i = tid; i < NCODE; i += 256) s2s[i] = g_s2[i];

    // A fragments (fp16) for this warp's 16 tokens
    const int r0 = tok0 + w * 16 + g, r1 = r0 + 8;
    uint32_t a[4][4];
#pragma unroll
    for (int ks = 0; ks < 4; ++ks) {
        const float* p0 = z + (size_t)r0 * DIM + ks * 16;
        const float* p1 = z + (size_t)r1 * DIM + ks * 16;
        float2 x0 = *(const float2*)(p0 + 2 * tg);
        float2 x1 = *(const float2*)(p1 + 2 * tg);
        float2 x2 = *(const float2*)(p0 + 8 + 2 * tg);
        float2 x3 = *(const float2*)(p1 + 8 + 2 * tg);
        a[ks][0] = h2(x0.x, x0.y);
        a[ks][1] = h2(x1.x, x1.y);
        a[ks][2] = h2(x2.x, x2.y);
        a[ks][3] = h2(x3.x, x3.y);
    }
    CP_WAIT0();
    __syncthreads();

    float best0 = 3.402823466e38f, sec0 = 3.402823466e38f;
    float best1 = 3.402823466e38f, sec1 = 3.402823466e38f;
    int bi0 = 0, bi1 = 0;

#pragma unroll 1
    for (int c = 0; c < 8; ++c) {
        if (c < 7) {
            const uint4* src = reinterpret_cast<const uint4*>(g_bfrag) + (c + 1) * 1024;
            uint32_t dst = sbf + (uint32_t)((c + 1) & 1) * 16384u;
#pragma unroll
            for (int i = 0; i < 4; ++i)
                CP_ASYNC16(dst + (uint32_t)(tid + i * 256) * 16, src + tid + i * 256);
            CP_COMMIT();
        }
        const uint2* bp = bf[c & 1] + lane;
        const float* s2c = s2s + c * 128;
#pragma unroll 1
        for (int nt = 0; nt < 16; nt += 4) {
            float acc[4][4];
#pragma unroll
            for (int j = 0; j < 4; ++j)
                acc[j][0] = acc[j][1] = acc[j][2] = acc[j][3] = 0.0f;
#pragma unroll
            for (int ks = 0; ks < 4; ++ks) {
#pragma unroll
                for (int j = 0; j < 4; ++j) {
                    uint2 B = bp[((nt + j) * 4 + ks) * 32];
                    mma_f16(acc[j][0], acc[j][1], acc[j][2], acc[j][3],
                            a[ks][0], a[ks][1], a[ks][2], a[ks][3], B.x, B.y);
                }
            }
#pragma unroll
            for (int j = 0; j < 4; ++j) {
                const int ntx = nt + j;
                const int j0 = c * 128 + ntx * 8 + 2 * tg;
                const float s2x = s2c[ntx * 8 + 2 * tg];
                const float s2y = s2c[ntx * 8 + 2 * tg + 1];
                // d~ = s2 - 2e  (s1 constant per token: irrelevant for argmin/gap)
                float d00 = __fmaf_rn(-2.0f, acc[j][0], s2x);
                float d01 = __fmaf_rn(-2.0f, acc[j][1], s2y);
                float d10 = __fmaf_rn(-2.0f, acc[j][2], s2x);
                float d11 = __fmaf_rn(-2.0f, acc[j][3], s2y);
                if (d00 < best0) { sec0 = best0; best0 = d00; bi0 = j0; }
                else if (d00 < sec0) sec0 = d00;
                if (d01 < best0) { sec0 = best0; best0 = d01; bi0 = j0 + 1; }
                else if (d01 < sec0) sec0 = d01;
                if (d10 < best1) { sec1 = best1; best1 = d10; bi1 = j0; }
                else if (d10 < sec1) sec1 = d10;
                if (d11 < best1) { sec1 = best1; best1 = d11; bi1 = j0 + 1; }
                else if (d11 < sec1) sec1 = d11;
            }
        }
        CP_WAIT0();
        __syncthreads();
    }

    // merge (best, second, idx) across the 4 tg-lanes of each row-group
#pragma unroll
    for (int m = 1; m <= 2; m <<= 1) {
        float ob = __shfl_xor_sync(0xffffffffu, best0, m);
        float os = __shfl_xor_sync(0xffffffffu, sec0, m);
        int   oi = __shfl_xor_sync(0xffffffffu, bi0, m);
        if (ob < best0 || (ob == best0 && oi < bi0)) { sec0 = fminf(best0, os); best0 = ob; bi0 = oi; }
        else sec0 = fminf(sec0, ob);
        ob = __shfl_xor_sync(0xffffffffu, best1, m);
        os = __shfl_xor_sync(0xffffffffu, sec1, m);
        oi = __shfl_xor_sync(0xffffffffu, bi1, m);
        if (ob < best1 || (ob == best1 && oi < bi1)) { sec1 = fminf(best1, os); best1 = ob; bi1 = oi; }
        else sec1 = fminf(sec1, ob);
    }
    if (tg == 0) {
        g_idx[r0] = bi0;
        g_idx[r1] = bi1;
        if (__fsub_rn(sec0, best0) <= THRESH) { int p = atomicAdd(&g_cnt, 1); g_list[p] = r0; }
        if (__fsub_rn(sec1, best1) <= THRESH) { int p = atomicAdd(&g_cnt, 1); g_list[p] = r1; }
    }
}

// -------- k_rescue: exact rescore of flagged tokens (R5 rounding chain) ----
__global__ void __launch_bounds__(128) k_rescue(const float* __restrict__ z,
                                                const float* __restrict__ cb) {
    __shared__ float cbs[64 * 64];
    __shared__ float s2s[64];
    __shared__ float zs[16][64];
    __shared__ float s1s[16];
    __shared__ int   toks[16];
    const int tid = threadIdx.x;
    const int cnt = g_cnt;

    for (int base = blockIdx.x * 16; base < cnt; base += gridDim.x * 16) {
        int nb = cnt - base; if (nb > 16) nb = 16;
        __syncthreads();
        if (tid < 16) toks[tid] = g_list[base + (tid < nb ? tid : 0)];
        __syncthreads();
        for (int i = tid; i < nb * 64; i += 128) {
            int t = i >> 6, d = i & 63;
            zs[t][d] = z[(size_t)toks[t] * 64 + d];
        }
        __syncthreads();
        if (tid < nb) {
            float s = 0.0f;
#pragma unroll
            for (int d = 0; d < 64; d++)
                s = __fadd_rn(s, __fmul_rn(zs[tid][d], zs[tid][d]));
            s1s[tid] = s;
        }
        float best = 3.402823466e38f;
        int bi = NCODE;
        const int tb = tid >> 3, sl = tid & 7;
        for (int c0 = 0; c0 < NCODE; c0 += 64) {
            __syncthreads();
            for (int i = tid; i < 64 * 64; i += 128) cbs[i] = cb[c0 * 64 + i];
            if (tid < 64) s2s[tid] = g_s2[c0 + tid];
            __syncthreads();
            if (tb < nb) {
#pragma unroll
                for (int half = 0; half < 2; ++half) {
                    const int k0 = sl + half * 32;
                    const float* cr0 = &cbs[k0 * 64];
                    const float* cr1 = &cbs[(k0 + 8) * 64];
                    const float* cr2 = &cbs[(k0 + 16) * 64];
                    const float* cr3 = &cbs[(k0 + 24) * 64];
                    float e0 = 0.f, e1 = 0.f, e2 = 0.f, e3 = 0.f;  // 4 exact chains
#pragma unroll
                    for (int d = 0; d < 64; d++) {
                        float zv = zs[tb][d];
                        e0 = __fmaf_rn(zv, cr0[d], e0);
                        e1 = __fmaf_rn(zv, cr1[d], e1);
                        e2 = __fmaf_rn(zv, cr2[d], e2);
                        e3 = __fmaf_rn(zv, cr3[d], e3);
                    }
                    float d0 = __fsub_rn(__fadd_rn(s1s[tb], s2s[k0]),      __fmul_rn(2.0f, e0));
                    float d1 = __fsub_rn(__fadd_rn(s1s[tb], s2s[k0 + 8]),  __fmul_rn(2.0f, e1));
                    float d2 = __fsub_rn(__fadd_rn(s1s[tb], s2s[k0 + 16]), __fmul_rn(2.0f, e2));
                    float d3 = __fsub_rn(__fadd_rn(s1s[tb], s2s[k0 + 24]), __fmul_rn(2.0f, e3));
                    if (d0 < best) { best = d0; bi = c0 + k0; }
                    if (d1 < best) { best = d1; bi = c0 + k0 + 8; }
                    if (d2 < best) { best = d2; bi = c0 + k0 + 16; }
                    if (d3 < best) { best = d3; bi = c0 + k0 + 24; }
                }
            }
        }
#pragma unroll
        for (int m = 4; m; m >>= 1) {
            float ob = __shfl_xor_sync(0xffffffffu, best, m);
            int   oi = __shfl_xor_sync(0xffffffffu, bi, m);
            if (ob < best || (ob == best && oi < bi)) { best = ob; bi = oi; }
        }
        if (sl == 0 && tb < nb) g_idx[toks[tb]] = bi;
    }
}

// -------- k_gather: 4 threads/token, warp-shuffle loss reduce ---------------
__global__ void __launch_bounds__(256) k_gather(const float* __restrict__ z,
                                                const float* __restrict__ cb,
                                                float* __restrict__ out) {
    const int u = blockIdx.x * 256 + threadIdx.x;   // [0, N_TOK*4)
    const int tok = u >> 2, q4 = u & 3;
    const int idx = g_idx[tok];
    const float4* zp = (const float4*)(z + (size_t)tok * 64 + q4 * 16);
    const float4* cp = (const float4*)(cb + (size_t)idx * 64 + q4 * 16);
    float4* op = (float4*)(out + (size_t)tok * 64 + q4 * 16);
    double ls = 0.0;
#pragma unroll
    for (int q = 0; q < 4; ++q) {
        float4 cv = cp[q], zv = zp[q], w;
        float df;
        df = __fsub_rn(cv.x, zv.x); w.x = __fadd_rn(zv.x, df); ls += (double)__fmul_rn(df, df);
        df = __fsub_rn(cv.y, zv.y); w.y = __fadd_rn(zv.y, df); ls += (double)__fmul_rn(df, df);
        df = __fsub_rn(cv.z, zv.z); w.z = __fadd_rn(zv.z, df); ls += (double)__fmul_rn(df, df);
        df = __fsub_rn(cv.w, zv.w); w.w = __fadd_rn(zv.w, df); ls += (double)__fmul_rn(df, df);
        op[q] = w;
    }
    if (q4 == 0) out[OUT_IDX + tok] = (float)idx;
#pragma unroll
    for (int m = 16; m; m >>= 1)
        ls += __shfl_xor_sync(0xffffffffu, ls, m);
    if ((threadIdx.x & 31) == 0) atomicAdd(&g_lacc, ls);
}

__global__ void k_fin(float* __restrict__ out) {
    double m = g_lacc / (double)((double)N_TOK * (double)DIM);
    float mf = (float)m;
    out[OUT_LOSS] = __fadd_rn(mf, mf);
}

extern "C" void kernel_launch(void* const* d_in, const int* in_sizes, int n_in,
                              void* d_out, int out_size) {
    const float* z = (const float*)d_in[0];
    const float* cb = (const float*)d_in[1];
    float* out = (float*)d_out;

    k_prep<<<NCODE * 16 / 256, 256>>>(cb);
    k_mma<<<N_TOK / 128, 256>>>(z);
    k_rescue<<<148, 128>>>(z, cb);
    k_gather<<<N_TOK * 4 / 256, 256>>>(z, cb, out);
    k_fin<<<1, 1>>>(out);
}

// round 12
// speedup vs baseline: 1.0062x; 1.0052x over previous
#include <cuda_runtime.h>
#include <cuda_fp16.h>
#include <cstdint>

// VQCodebook: single-product fp16 HMMA (R8 loop skeleton) + packed-key argmin
// + exact fp32 rescue of near-ties.
// Out (f32): [z_q_st 65536*64][indices 65536][loss 1]

#define N_TOK   65536
#define DIM     64
#define NCODE   1024
#define OUT_IDX (N_TOK * DIM)
#define OUT_LOSS (OUT_IDX + N_TOK)
#define THRESH  2e-4f

// B fragments: [chunk][pair][ks][lane] -> uint4 {nt_even b0,b1, nt_odd b0,b1}
// stored as uint2 pairs so two codes can write halves independently.
__device__ uint2  g_bf2[8 * 8 * 4 * 32 * 2];
__device__ float  g_s2[NCODE];
__device__ int    g_idx[N_TOK];
__device__ int    g_list[N_TOK];
__device__ int    g_cnt;
__device__ double g_lacc;

__device__ __forceinline__ uint32_t smem_u32(const void* p) {
    uint32_t a;
    asm("{ .reg .u64 t; cvta.to.shared.u64 t, %1; cvt.u32.u64 %0, t; }" : "=r"(a) : "l"(p));
    return a;
}
__device__ __forceinline__ uint32_t h2(float x, float y) {
    __half2 h = __floats2half2_rn(x, y);
    return *reinterpret_cast<uint32_t*>(&h);
}
__device__ __forceinline__ void mma_f16(float& c0, float& c1, float& c2, float& c3,
                                        uint32_t a0, uint32_t a1, uint32_t a2, uint32_t a3,
                                        uint32_t b0, uint32_t b1) {
    asm volatile("mma.sync.aligned.m16n8k16.row.col.f32.f16.f16.f32 "
                 "{%0,%1,%2,%3}, {%4,%5,%6,%7}, {%8,%9}, {%0,%1,%2,%3};"
                 : "+f"(c0), "+f"(c1), "+f"(c2), "+f"(c3)
                 : "r"(a0), "r"(a1), "r"(a2), "r"(a3), "r"(b0), "r"(b1));
}
// monotone float->uint key (finite inputs), and inverse
__device__ __forceinline__ uint32_t fkey(float d) {
    uint32_t u = __float_as_uint(d);
    return u ^ ((uint32_t)((int32_t)u >> 31) | 0x80000000u);
}
__device__ __forceinline__ float funkey(uint32_t k) {
    uint32_t u = (k & 0x80000000u) ? (k ^ 0x80000000u) : ~k;
    return __uint_as_float(u);
}
#define CP_ASYNC16(dst, src) \
    asm volatile("cp.async.cg.shared.global [%0], [%1], 16;" :: "r"(dst), "l"(src))
#define CP_COMMIT() asm volatile("cp.async.commit_group;" ::: "memory")
#define CP_WAIT0()  asm volatile("cp.async.wait_group 0;" ::: "memory")

// -------- k_prep: exact code norms + paired fp16 fragment codebook ---------
// 16 threads per code: sub -> (ks = sub>>2, tg = sub&3); sub 0 also does norm.
__global__ void __launch_bounds__(256) k_prep(const float* __restrict__ cb) {
    const int t = blockIdx.x * blockDim.x + threadIdx.x;   // [0, NCODE*16)
    if (t == 0) { g_lacc = 0.0; g_cnt = 0; }
    const int k = t >> 4, sub = t & 15;
    if (k >= NCODE) return;
    const float* r = cb + (size_t)k * DIM;

    if (sub == 0) {
        float s = 0.0f;
#pragma unroll
        for (int d = 0; d < DIM; ++d)
            s = __fadd_rn(s, __fmul_rn(r[d], r[d]));
        g_s2[k] = s;
    }
    const int ks = sub >> 2, tg = sub & 3;
    const int base = 16 * ks;
    uint32_t b0 = h2(r[base + 2 * tg],     r[base + 2 * tg + 1]);
    uint32_t b1 = h2(r[base + 8 + 2 * tg], r[base + 8 + 2 * tg + 1]);
    const int chunk = k >> 7, cc = k & 127;
    const int nt = cc >> 3, n = cc & 7;
    const int p = nt >> 1, h = nt & 1;
    g_bf2[((((chunk * 8 + p) * 4 + ks) * 32) + n * 4 + tg) * 2 + h] = make_uint2(b0, b1);
}

// -------- k_mma: 128 tokens/CTA, R8 skeleton, single fp16 product ----------
__global__ void __launch_bounds__(256, 3) k_mma(const float* __restrict__ z) {
    __shared__ __align__(16) uint4 bf[2][1024];   // 2 x 16KB
    __shared__ float s2s[NCODE];                  // 4KB
    const uint32_t sbf = smem_u32(bf);
    const int tid = threadIdx.x;
    const int w = tid >> 5, lane = tid & 31;
    const int g = lane >> 2, tg = lane & 3;
    const int tok0 = blockIdx.x * 128;

    // stage chunk 0 into buf0 (16KB = 1024 uint4)
    {
        const uint4* src = reinterpret_cast<const uint4*>(g_bf2);
#pragma unroll
        for (int i = 0; i < 4; ++i)
            CP_ASYNC16(sbf + (uint32_t)(tid + i * 256) * 16, src + tid + i * 256);
        CP_COMMIT();
    }
    for (int i = tid; i < NCODE; i += 256) s2s[i] = g_s2[i];

    // A fragments (fp16) for this warp's 16 tokens
    const int r0 = tok0 + w * 16 + g, r1 = r0 + 8;
    uint32_t a0[4], a1[4], a2[4], a3[4];
#pragma unroll
    for (int ks = 0; ks < 4; ++ks) {
        const float* p0 = z + (size_t)r0 * DIM + ks * 16;
        const float* p1 = z + (size_t)r1 * DIM + ks * 16;
        float2 x0 = *(const float2*)(p0 + 2 * tg);
        float2 x1 = *(const float2*)(p1 + 2 * tg);
        float2 x2 = *(const float2*)(p0 + 8 + 2 * tg);
        float2 x3 = *(const float2*)(p1 + 8 + 2 * tg);
        a0[ks] = h2(x0.x, x0.y);
        a1[ks] = h2(x1.x, x1.y);
        a2[ks] = h2(x2.x, x2.y);
        a3[ks] = h2(x3.x, x3.y);
    }
    CP_WAIT0();
    __syncthreads();

    uint32_t best0 = 0xFFFFFFFFu, sec0 = 0xFFFFFFFFu;
    uint32_t best1 = 0xFFFFFFFFu, sec1 = 0xFFFFFFFFu;

#pragma unroll 1
    for (int c = 0; c < 8; ++c) {
        if (c < 7) {
            const uint4* src = reinterpret_cast<const uint4*>(g_bf2) + (c + 1) * 1024;
            uint32_t dst = sbf + (uint32_t)((c + 1) & 1) * 16384u;
#pragma unroll
            for (int i = 0; i < 4; ++i)
                CP_ASYNC16(dst + (uint32_t)(tid + i * 256) * 16, src + tid + i * 256);
            CP_COMMIT();
        }
        const uint4* bp = bf[c & 1] + lane;
        const float* s2c = s2s + c * 128;
#pragma unroll 1
        for (int p = 0; p < 8; ++p) {
            float p0 = 0.f, p1 = 0.f, p2 = 0.f, p3 = 0.f;   // nt even
            float q0 = 0.f, q1 = 0.f, q2 = 0.f, q3 = 0.f;   // nt odd
#pragma unroll
            for (int ks = 0; ks < 4; ++ks) {
                uint4 B = bp[(p * 4 + ks) * 32];
                mma_f16(p0, p1, p2, p3, a0[ks], a1[ks], a2[ks], a3[ks], B.x, B.y);
                mma_f16(q0, q1, q2, q3, a0[ks], a1[ks], a2[ks], a3[ks], B.z, B.w);
            }
            // distances: d~ = s2 - 2e (s1 dropped: constant per token)
            const int jb = c * 128 + p * 16 + 2 * tg;        // nt even, col pair
            const float s2x0 = s2c[p * 16 + 2 * tg];
            const float s2y0 = s2c[p * 16 + 2 * tg + 1];
            const float s2x1 = s2c[p * 16 + 8 + 2 * tg];
            const float s2y1 = s2c[p * 16 + 8 + 2 * tg + 1];
            uint32_t k00 = (fkey(__fmaf_rn(-2.0f, p0, s2x0)) & 0xFFFFFC00u) | (uint32_t)(jb);
            uint32_t k01 = (fkey(__fmaf_rn(-2.0f, p1, s2y0)) & 0xFFFFFC00u) | (uint32_t)(jb + 1);
            uint32_t k10 = (fkey(__fmaf_rn(-2.0f, p2, s2x0)) & 0xFFFFFC00u) | (uint32_t)(jb);
            uint32_t k11 = (fkey(__fmaf_rn(-2.0f, p3, s2y0)) & 0xFFFFFC00u) | (uint32_t)(jb + 1);
            uint32_t m00 = (fkey(__fmaf_rn(-2.0f, q0, s2x1)) & 0xFFFFFC00u) | (uint32_t)(jb + 8);
            uint32_t m01 = (fkey(__fmaf_rn(-2.0f, q1, s2y1)) & 0xFFFFFC00u) | (uint32_t)(jb + 9);
            uint32_t m10 = (fkey(__fmaf_rn(-2.0f, q2, s2x1)) & 0xFFFFFC00u) | (uint32_t)(jb + 8);
            uint32_t m11 = (fkey(__fmaf_rn(-2.0f, q3, s2y1)) & 0xFFFFFC00u) | (uint32_t)(jb + 9);
            // predicate-free best/second chains (umin/umax)
            sec0 = min(sec0, max(best0, k00)); best0 = min(best0, k00);
            sec0 = min(sec0, max(best0, k01)); best0 = min(best0, k01);
            sec0 = min(sec0, max(best0, m00)); best0 = min(best0, m00);
            sec0 = min(sec0, max(best0, m01)); best0 = min(best0, m01);
            sec1 = min(sec1, max(best1, k10)); best1 = min(best1, k10);
            sec1 = min(sec1, max(best1, k11)); best1 = min(best1, k11);
            sec1 = min(sec1, max(best1, m10)); best1 = min(best1, m10);
            sec1 = min(sec1, max(best1, m11)); best1 = min(best1, m11);
        }
        CP_WAIT0();
        __syncthreads();
    }

    // merge across the 4 tg-lanes of each row-group (keys are globally ordered)
#pragma unroll
    for (int m = 1; m <= 2; m <<= 1) {
        uint32_t ob = __shfl_xor_sync(0xffffffffu, best0, m);
        uint32_t os = __shfl_xor_sync(0xffffffffu, sec0, m);
        sec0 = min(min(sec0, os), max(best0, ob));
        best0 = min(best0, ob);
        ob = __shfl_xor_sync(0xffffffffu, best1, m);
        os = __shfl_xor_sync(0xffffffffu, sec1, m);
        sec1 = min(min(sec1, os), max(best1, ob));
        best1 = min(best1, ob);
    }
    if (tg == 0) {
        const int bi0 = (int)(best0 & 1023u);
        const int bi1 = (int)(best1 & 1023u);
        g_idx[r0] = bi0;
        g_idx[r1] = bi1;
        float gap0 = funkey(sec0 & 0xFFFFFC00u) - funkey(best0 & 0xFFFFFC00u);
        float gap1 = funkey(sec1 & 0xFFFFFC00u) - funkey(best1 & 0xFFFFFC00u);
        if (gap0 <= THRESH) { int q = atomicAdd(&g_cnt, 1); g_list[q] = r0; }
        if (gap1 <= THRESH) { int q = atomicAdd(&g_cnt, 1); g_list[q] = r1; }
    }
}

// -------- k_rescue: exact rescore of flagged tokens (R5 rounding chain) ----
__global__ void __launch_bounds__(128) k_rescue(const float* __restrict__ z,
                                                const float* __restrict__ cb) {
    __shared__ float cbs[64 * 64];
    __shared__ float s2s[64];
    __shared__ float zs[16][64];
    __shared__ float s1s[16];
    __shared__ int   toks[16];
    const int tid = threadIdx.x;
    const int cnt = g_cnt;

    for (int base = blockIdx.x * 16; base < cnt; base += gridDim.x * 16) {
        int nb = cnt - base; if (nb > 16) nb = 16;
        __syncthreads();
        if (tid < 16) toks[tid] = g_list[base + (tid < nb ? tid : 0)];
        __syncthreads();
        for (int i = tid; i < nb * 64; i += 128) {
            int t = i >> 6, d = i & 63;
            zs[t][d] = z[(size_t)toks[t] * 64 + d];
        }
        __syncthreads();
        if (tid < nb) {
            float s = 0.0f;
#pragma unroll
            for (int d = 0; d < 64; d++)
                s = __fadd_rn(s, __fmul_rn(zs[tid][d], zs[tid][d]));
            s1s[tid] = s;
        }
        float best = 3.402823466e38f;
        int bi = NCODE;
        const int tb = tid >> 3, sl = tid & 7;
        for (int c0 = 0; c0 < NCODE; c0 += 64) {
            __syncthreads();
            for (int i = tid; i < 64 * 64; i += 128) cbs[i] = cb[c0 * 64 + i];
            if (tid < 64) s2s[tid] = g_s2[c0 + tid];
            __syncthreads();
            if (tb < nb) {
#pragma unroll
                for (int half = 0; half < 2; ++half) {
                    const int k0 = sl + half * 32;
                    const float* cr0 = &cbs[k0 * 64];
                    const float* cr1 = &cbs[(k0 + 8) * 64];
                    const float* cr2 = &cbs[(k0 + 16) * 64];
                    const float* cr3 = &cbs[(k0 + 24) * 64];
                    float e0 = 0.f, e1 = 0.f, e2 = 0.f, e3 = 0.f;  // 4 exact chains
#pragma unroll
                    for (int d = 0; d < 64; d++) {
                        float zv = zs[tb][d];
                        e0 = __fmaf_rn(zv, cr0[d], e0);
                        e1 = __fmaf_rn(zv, cr1[d], e1);
                        e2 = __fmaf_rn(zv, cr2[d], e2);
                        e3 = __fmaf_rn(zv, cr3[d], e3);
                    }
                    float d0 = __fsub_rn(__fadd_rn(s1s[tb], s2s[k0]),      __fmul_rn(2.0f, e0));
                    float d1 = __fsub_rn(__fadd_rn(s1s[tb], s2s[k0 + 8]),  __fmul_rn(2.0f, e1));
                    float d2 = __fsub_rn(__fadd_rn(s1s[tb], s2s[k0 + 16]), __fmul_rn(2.0f, e2));
                    float d3 = __fsub_rn(__fadd_rn(s1s[tb], s2s[k0 + 24]), __fmul_rn(2.0f, e3));
                    if (d0 < best) { best = d0; bi = c0 + k0; }
                    if (d1 < best) { best = d1; bi = c0 + k0 + 8; }
                    if (d2 < best) { best = d2; bi = c0 + k0 + 16; }
                    if (d3 < best) { best = d3; bi = c0 + k0 + 24; }
                }
            }
        }
#pragma unroll
        for (int m = 4; m; m >>= 1) {
            float ob = __shfl_xor_sync(0xffffffffu, best, m);
            int   oi = __shfl_xor_sync(0xffffffffu, bi, m);
            if (ob < best || (ob == best && oi < bi)) { best = ob; bi = oi; }
        }
        if (sl == 0 && tb < nb) g_idx[toks[tb]] = bi;
    }
}

// -------- k_gather: 2 threads/token, warp-shuffle loss reduce ---------------
__global__ void __launch_bounds__(256) k_gather(const float* __restrict__ z,
                                                const float* __restrict__ cb,
                                                float* __restrict__ out) {
    const int u = blockIdx.x * 256 + threadIdx.x;   // [0, N_TOK*2)
    const int tok = u >> 1, half = u & 1;
    const int idx = g_idx[tok];
    const float4* zp = (const float4*)(z + (size_t)tok * 64 + half * 32);
    const float4* cp = (const float4*)(cb + (size_t)idx * 64 + half * 32);
    float4* op = (float4*)(out + (size_t)tok * 64 + half * 32);
    double ls = 0.0;
#pragma unroll
    for (int q = 0; q < 8; ++q) {
        float4 cv = cp[q], zv = zp[q], w;
        float df;
        df = __fsub_rn(cv.x, zv.x); w.x = __fadd_rn(zv.x, df); ls += (double)__fmul_rn(df, df);
        df = __fsub_rn(cv.y, zv.y); w.y = __fadd_rn(zv.y, df); ls += (double)__fmul_rn(df, df);
        df = __fsub_rn(cv.z, zv.z); w.z = __fadd_rn(zv.z, df); ls += (double)__fmul_rn(df, df);
        df = __fsub_rn(cv.w, zv.w); w.w = __fadd_rn(zv.w, df); ls += (double)__fmul_rn(df, df);
        op[q] = w;
    }
    if (half == 0) out[OUT_IDX + tok] = (float)idx;
#pragma unroll
    for (int m = 16; m; m >>= 1)
        ls += __shfl_xor_sync(0xffffffffu, ls, m);
    if ((threadIdx.x & 31) == 0) atomicAdd(&g_lacc, ls);
}

__global__ void k_fin(float* __restrict__ out) {
    double m = g_lacc / (double)((double)N_TOK * (double)DIM);
    float mf = (float)m;
    out[OUT_LOSS] = __fadd_rn(mf, mf);
}

extern "C" void kernel_launch(void* const* d_in, const int* in_sizes, int n_in,
                              void* d_out, int out_size) {
    const float* z = (const float*)d_in[0];
    const float* cb = (const float*)d_in[1];
    float* out = (float*)d_out;

    k_prep<<<NCODE * 16 / 256, 256>>>(cb);
    k_mma<<<N_TOK / 128, 256>>>(z);
    k_rescue<<<148, 128>>>(z, cb);
    k_gather<<<N_TOK * 2 / 256, 256>>>(z, cb, out);
    k_fin<<<1, 1>>>(out);
}